// round 13
// baseline (speedup 1.0000x reference)
#include <cuda_runtime.h>
#include <cuda_fp16.h>
#include <cstdint>

#define DDIM    64
#define KCODES  1024
#define NCHUNK  8
#define CPC     128          // codes per chunk
#define NSUB    4            // n32 subtiles per chunk
#define BLOCK   256          // 8 warps, 16 rows/warp -> 128 rows per block
#define RESCORE_TAU 2e-3f

// ---------------- device scratch (allocation-free rule) ----------------
__device__ float g_esq[KCODES];
// fp16 codebook fragments: [chunk][ks(4)][ntile(16)][lane(32)] -> {b0,b1}  (128 KB)
__device__ uint2 g_bfrag[NCHUNK][4][16][32];
__device__ float g_partials[1024];

// ---------------- helpers ----------------
__device__ __forceinline__ uint32_t packh(float lo, float hi) {
    __half2 h = __floats2half2_rn(lo, hi);
    return *reinterpret_cast<uint32_t*>(&h);
}
#define MMA16816(D, A, b0v, b1v)                                             \
    asm volatile("mma.sync.aligned.m16n8k16.row.col.f32.f16.f16.f32 "        \
                 "{%0,%1,%2,%3}, {%4,%5,%6,%7}, {%8,%9}, {%0,%1,%2,%3};"     \
                 : "+f"((D)[0]), "+f"((D)[1]), "+f"((D)[2]), "+f"((D)[3])    \
                 : "r"((A)[0]), "r"((A)[1]), "r"((A)[2]), "r"((A)[3]),       \
                   "r"(b0v), "r"(b1v))

#define CP_ASYNC16(saddr, gptr) \
    asm volatile("cp.async.cg.shared.global [%0], [%1], 16;" :: "r"(saddr), "l"(gptr) : "memory")
#define CP_COMMIT() asm volatile("cp.async.commit_group;" ::: "memory")
#define CP_WAIT0()  asm volatile("cp.async.wait_group 0;" ::: "memory")

__device__ __forceinline__ uint32_t smem_u32(const void* p) {
    uint32_t a;
    asm("{ .reg .u64 t; cvta.to.shared.u64 t, %1; cvt.u32.u64 %0, t; }" : "=r"(a) : "l"(p));
    return a;
}
// reference-coarse distance: fl32(fl32(xsq+esq) - fl32(2*dot))
__device__ __forceinline__ float coarse_dist(float xsq, float esq, float dotf) {
    float t = __fadd_rn(xsq, esq);
    return __fadd_rn(t, -__fmul_rn(2.0f, dotf));
}
// embed 10-bit GLOBAL code into low mantissa bits
__device__ __forceinline__ float keyed(float d, uint32_t code) {
    return __uint_as_float((__float_as_uint(d) & 0xFFFFFC00u) | code);
}

// ---------------- prep (merged): |e|^2 + fp16 B fragments ----------------
// NEEDS >= 16384 threads: one thread per g_bfrag entry.
__global__ void prep(const float* __restrict__ emb) {
    int idx = blockIdx.x * blockDim.x + threadIdx.x;   // 16384 threads
    {
        int lane = idx & 31;
        int ntg  = (idx >> 5) & 15;
        int ks   = (idx >> 9) & 3;
        int c    = idx >> 11;
        if (c < NCHUNK) {
            int g = lane >> 2, t = lane & 3;
            int n = c * CPC + ntg * 8 + g;
            const float* e = emb + (size_t)n * DDIM + ks * 16;
            g_bfrag[c][ks][ntg][lane] =
                make_uint2(packh(e[2 * t], e[2 * t + 1]),
                           packh(e[2 * t + 8], e[2 * t + 9]));
        }
    }
    if (idx < KCODES) {
        const float4* e = (const float4*)(emb + (size_t)idx * DDIM);
        float s = 0.f;
#pragma unroll
        for (int i = 0; i < 16; i++) {
            float4 v = e[i];
            s += v.x * v.x + v.y * v.y + v.z * v.z + v.w * v.w;
        }
        g_esq[idx] = s;
    }
}

// ---------------- main kernel: 16 rows/warp, 1-pass fp16, guarded min-first top-3 ----------------
__global__ __launch_bounds__(BLOCK, 3) void vq_main(
    const float* __restrict__ x, const float* __restrict__ emb,
    float* __restrict__ out, int N)
{
    __shared__ uint2 s_bfrag[2][4][16][32];   // 2 x 16 KB double buffer
    __shared__ float s_esq[KCODES];           // 4 KB
    __shared__ float s_red[BLOCK / 32];
    const uint32_t sb_frag = smem_u32(&s_bfrag[0][0][0][0]);

    const int tid = threadIdx.x, wid = tid >> 5, lane = tid & 31;
    const int g = lane >> 2, t = lane & 3;
    const int base = blockIdx.x * 128 + wid * 16;   // 16 rows per warp

    // ---- A fragments: plain fp16 (rescore machinery absorbs the error) ----
    uint32_t Ah[4][4];
    {
        const float* r0 = x + (size_t)(base + g) * DDIM;
        const float* r8 = r0 + 8 * DDIM;
#pragma unroll
        for (int ks = 0; ks < 4; ks++) {
            const float2* p0 = (const float2*)(r0 + ks * 16);
            const float2* p8 = (const float2*)(r8 + ks * 16);
            float2 v0a = p0[t], v0b = p0[t + 4];
            float2 v8a = p8[t], v8b = p8[t + 4];
            Ah[ks][0] = packh(v0a.x, v0a.y);
            Ah[ks][1] = packh(v8a.x, v8a.y);
            Ah[ks][2] = packh(v0b.x, v0b.y);
            Ah[ks][3] = packh(v8b.x, v8b.y);
        }
    }

    // ---- esq into smem + prefetch chunk 0 (16 KB) ----
    {
        const char* src = (const char*)&g_bfrag[0][0][0][0];
#pragma unroll
        for (int i = 0; i < 4; i++)
            CP_ASYNC16(sb_frag + tid * 16 + i * 4096, src + tid * 16 + i * 4096);
        CP_COMMIT();
        for (int i = tid; i < KCODES; i += BLOCK) s_esq[i] = g_esq[i];
    }
    CP_WAIT0();
    __syncthreads();

    // keyed top-3 per row (j=0: row g, j=1: row g+8), 10-bit global code key
    float fc1[2] = {3.4e38f, 3.4e38f};
    float fc2[2] = {3.4e38f, 3.4e38f};
    float fc3[2] = {3.4e38f, 3.4e38f};

// streaming top-3 insert of an already-keyed value (exact no-op when _f > fc3)
#define TOP3_RAW(j, _f) do {                                        \
        float _t0 = fmaxf(fc1[j], _f); fc1[j] = fminf(fc1[j], _f);  \
        float _t1 = fmaxf(fc2[j], _t0); fc2[j] = fminf(fc2[j], _t0);\
        fc3[j] = fminf(fc3[j], _t1);                                \
    } while (0)

    for (int c = 0; c < NCHUNK; c++) {
        const int cur = c & 1;
        if (c < NCHUNK - 1) {   // prefetch next chunk into other buffer
            const char* src = (const char*)&g_bfrag[c + 1][0][0][0];
            const uint32_t dst = sb_frag + (cur ^ 1) * 16384;
#pragma unroll
            for (int i = 0; i < 4; i++)
                CP_ASYNC16(dst + tid * 16 + i * 4096, src + tid * 16 + i * 4096);
            CP_COMMIT();
        }
        const uint2* bf = &s_bfrag[cur][0][0][0];

#pragma unroll
        for (int sub = 0; sub < NSUB; sub++) {
            float acc[4][4];
#pragma unroll
            for (int nt = 0; nt < 4; nt++)
#pragma unroll
                for (int q = 0; q < 4; q++) acc[nt][q] = 0.f;

            // single fp16 pass: dot = fl16(x) . fl16(e), fp32 accumulate
#pragma unroll
            for (int ks = 0; ks < 4; ks++) {
                uint2 b[4];
#pragma unroll
                for (int nt = 0; nt < 4; nt++)
                    b[nt] = bf[(ks * 16 + sub * 4 + nt) * 32 + lane];
#pragma unroll
                for (int nt = 0; nt < 4; nt++)
                    MMA16816(acc[nt], Ah[ks], b[nt].x, b[nt].y);
            }

            // epilogue v2: key in place (parallel), per-row min tree,
            // guarded rare insert (exact: f >= fc3 is a provable no-op)
#pragma unroll
            for (int nt = 0; nt < 4; nt++) {
                const int ntg = sub * 4 + nt;
                float2 es = *(const float2*)&s_esq[c * CPC + ntg * 8 + 2 * t];
                const uint32_t k0 = (uint32_t)(c * CPC + ntg * 8 + 2 * t);
                acc[nt][0] = keyed(fmaf(-2.f, acc[nt][0], es.x), k0);
                acc[nt][1] = keyed(fmaf(-2.f, acc[nt][1], es.y), k0 + 1);
                acc[nt][2] = keyed(fmaf(-2.f, acc[nt][2], es.x), k0);
                acc[nt][3] = keyed(fmaf(-2.f, acc[nt][3], es.y), k0 + 1);
            }
#pragma unroll
            for (int j = 0; j < 2; j++) {
                float m = fminf(
                    fminf(fminf(acc[0][2*j], acc[0][2*j+1]), fminf(acc[1][2*j], acc[1][2*j+1])),
                    fminf(fminf(acc[2][2*j], acc[2][2*j+1]), fminf(acc[3][2*j], acc[3][2*j+1])));
                if (m < fc3[j]) {
#pragma unroll
                    for (int nt = 0; nt < 4; nt++) {
                        TOP3_RAW(j, acc[nt][2*j]);
                        TOP3_RAW(j, acc[nt][2*j+1]);
                    }
                }
            }
        }

        if (c < NCHUNK - 1) CP_WAIT0();
        __syncthreads();
    }

    // ---- merge sorted top-3 across the 4-lane t-group (keyed values are distinct) ----
#pragma unroll
    for (int off = 1; off <= 2; off <<= 1) {
#pragma unroll
        for (int j = 0; j < 2; j++) {
            float o1 = __shfl_xor_sync(0xffffffffu, fc1[j], off);
            float o2 = __shfl_xor_sync(0xffffffffu, fc2[j], off);
            float o3 = __shfl_xor_sync(0xffffffffu, fc3[j], off);
            float hi1 = fmaxf(fc1[j], o1), c1 = fminf(fc1[j], o1);
            float lo2 = fminf(fc2[j], o2), hi2 = fmaxf(fc2[j], o2);
            float lo3 = fminf(fc3[j], o3);
            float c2 = fminf(hi1, lo2);
            float c3 = fminf(fmaxf(hi1, lo2), fminf(hi2, lo3));
            fc1[j] = c1; fc2[j] = c2; fc3[j] = c3;
        }
    }

    // ---- decode + near-tie rescore with the REFERENCE's coarse fp32 arithmetic ----
    int gi[2];
#pragma unroll
    for (int j = 0; j < 2; j++) {
        uint32_t b1 = __float_as_uint(fc1[j]);
        uint32_t b2 = __float_as_uint(fc2[j]);
        uint32_t b3 = __float_as_uint(fc3[j]);
        int   i1 = (int)(b1 & 1023u), i2 = (int)(b2 & 1023u), i3 = (int)(b3 & 1023u);
        float f1 = __uint_as_float(b1 & 0xFFFFFC00u);
        float f2 = __uint_as_float(b2 & 0xFFFFFC00u);
        float f3 = __uint_as_float(b3 & 0xFFFFFC00u);
        gi[j] = i1;
        if (f2 - f1 < RESCORE_TAU) {
            const int row = base + j * 8 + g;
            const float* xr = x + (size_t)row * DDIM;
            float xsq = 0.f;
            for (int k = 0; k < DDIM; k++)
                xsq = __fadd_rn(xsq, __fmul_rn(xr[k], xr[k]));
            const bool use3 = (f3 - f1 < RESCORE_TAU);
            const float* e1 = emb + (size_t)i1 * DDIM;
            const float* e2 = emb + (size_t)i2 * DDIM;
            const float* e3 = emb + (size_t)i3 * DDIM;
            double d1 = 0.0, d2 = 0.0, d3 = 0.0;
            for (int k = 0; k < DDIM; k++) {
                double xv = (double)xr[k];
                d1 = fma(xv, (double)e1[k], d1);
                d2 = fma(xv, (double)e2[k], d2);
                if (use3) d3 = fma(xv, (double)e3[k], d3);
            }
            float c1d = coarse_dist(xsq, g_esq[i1], (float)d1);
            float c2d = coarse_dist(xsq, g_esq[i2], (float)d2);
            int   bi = i1; float bd = c1d;
            if (c2d < bd || (c2d == bd && i2 < bi)) { bd = c2d; bi = i2; }
            if (use3) {
                float c3d = coarse_dist(xsq, g_esq[i3], (float)d3);
                if (c3d < bd || (c3d == bd && i3 < bi)) { bd = c3d; bi = i3; }
            }
            gi[j] = bi;
        }
    }

    // ---- outputs: quant gather (exact fp32), indices, exact loss partial ----
    float errsum = 0.f;
#pragma unroll
    for (int j = 0; j < 2; j++) {
        const int row = base + j * 8 + g;
        const int idx = gi[j];
        if (t == 0) out[(size_t)N * DDIM + 1 + row] = (float)idx;
        const float4* ep = (const float4*)(emb + (size_t)idx * DDIM + t * 16);
        const float4* xp = (const float4*)(x + (size_t)row * DDIM + t * 16);
        float4* op = (float4*)(out + (size_t)row * DDIM + t * 16);
#pragma unroll
        for (int q = 0; q < 4; q++) {
            float4 e = ep[q], v = xp[q];
            op[q] = e;
            float d0 = e.x - v.x, d1 = e.y - v.y, d2 = e.z - v.z, d3 = e.w - v.w;
            errsum += d0 * d0 + d1 * d1 + d2 * d2 + d3 * d3;
        }
    }
#pragma unroll
    for (int o = 16; o; o >>= 1) errsum += __shfl_down_sync(0xffffffffu, errsum, o);
    if (lane == 0) s_red[wid] = errsum;
    __syncthreads();
    if (tid == 0) {
        float s = 0.f;
#pragma unroll
        for (int w = 0; w < BLOCK / 32; w++) s += s_red[w];
        g_partials[blockIdx.x] = s;
    }
}

// ---------------- final loss reduction (1024 threads = 32 warps) ----------------
__global__ void loss_kernel(float* __restrict__ out, int nblocks, int N) {
    __shared__ float s_red[32];
    float v = 0.f;
    for (int i = threadIdx.x; i < nblocks; i += blockDim.x) v += g_partials[i];
#pragma unroll
    for (int o = 16; o; o >>= 1) v += __shfl_down_sync(0xffffffffu, v, o);
    if ((threadIdx.x & 31) == 0) s_red[threadIdx.x >> 5] = v;
    __syncthreads();
    if (threadIdx.x < 32) {
        float tt = (threadIdx.x < (int)(blockDim.x >> 5)) ? s_red[threadIdx.x] : 0.f;
#pragma unroll
        for (int o = 16; o; o >>= 1) tt += __shfl_down_sync(0xffffffffu, tt, o);
        if (threadIdx.x == 0)
            out[(size_t)N * DDIM] = 1.25f * tt / ((float)N * (float)DDIM);
    }
}

// ---------------------------------------------------------------------------
extern "C" void kernel_launch(void* const* d_in, const int* in_sizes, int n_in,
                              void* d_out, int out_size) {
    const float* x   = (const float*)d_in[0];   // [B,T,D] fp32
    const float* emb = (const float*)d_in[1];   // [K,D]  fp32
    float* out = (float*)d_out;                 // [N*D quant | 1 loss | N idx]
    const int N  = in_sizes[0] / DDIM;          // 131072
    const int nb = N / 128;                     // 1024

    prep<<<64, 256>>>(emb);
    vq_main<<<nb, BLOCK>>>(x, emb, out, N);
    loss_kernel<<<1, 1024>>>(out, nb, N);
}

// round 14
// speedup vs baseline: 1.0668x; 1.0668x over previous
#include <cuda_runtime.h>
#include <cuda_fp16.h>
#include <cstdint>

#define DDIM    64
#define KCODES  1024
#define NCHUNK  8
#define CPC     128          // codes per chunk
#define NSUB    4            // n32 subtiles per chunk
#define BLOCK   256          // 8 warps, 16 rows/warp -> 128 rows per block
#define RESCORE_TAU 2e-3f

// ---------------- device scratch (allocation-free rule) ----------------
__device__ float g_esq[KCODES];
// fp16 codebook fragments: [chunk][ks(4)][ntile(16)][lane(32)] -> {b0,b1}  (128 KB)
__device__ uint2 g_bfrag[NCHUNK][4][16][32];
__device__ float g_partials[1024];

// ---------------- helpers ----------------
__device__ __forceinline__ uint32_t packh(float lo, float hi) {
    __half2 h = __floats2half2_rn(lo, hi);
    return *reinterpret_cast<uint32_t*>(&h);
}
#define MMA16816(D, A, b0v, b1v)                                             \
    asm volatile("mma.sync.aligned.m16n8k16.row.col.f32.f16.f16.f32 "        \
                 "{%0,%1,%2,%3}, {%4,%5,%6,%7}, {%8,%9}, {%0,%1,%2,%3};"     \
                 : "+f"((D)[0]), "+f"((D)[1]), "+f"((D)[2]), "+f"((D)[3])    \
                 : "r"((A)[0]), "r"((A)[1]), "r"((A)[2]), "r"((A)[3]),       \
                   "r"(b0v), "r"(b1v))

#define CP_ASYNC16(saddr, gptr) \
    asm volatile("cp.async.cg.shared.global [%0], [%1], 16;" :: "r"(saddr), "l"(gptr) : "memory")
#define CP_COMMIT() asm volatile("cp.async.commit_group;" ::: "memory")
#define CP_WAIT0()  asm volatile("cp.async.wait_group 0;" ::: "memory")

__device__ __forceinline__ uint32_t smem_u32(const void* p) {
    uint32_t a;
    asm("{ .reg .u64 t; cvta.to.shared.u64 t, %1; cvt.u32.u64 %0, t; }" : "=r"(a) : "l"(p));
    return a;
}
// reference-coarse distance: fl32(fl32(xsq+esq) - fl32(2*dot))
__device__ __forceinline__ float coarse_dist(float xsq, float esq, float dotf) {
    float t = __fadd_rn(xsq, esq);
    return __fadd_rn(t, -__fmul_rn(2.0f, dotf));
}
// embed 10-bit GLOBAL code into low mantissa bits
__device__ __forceinline__ float keyed(float d, uint32_t code) {
    return __uint_as_float((__float_as_uint(d) & 0xFFFFFC00u) | code);
}

// ---------------- prep (merged): |e|^2 + fp16 B fragments ----------------
// NEEDS >= 16384 threads: one thread per g_bfrag entry.
__global__ void prep(const float* __restrict__ emb) {
    int idx = blockIdx.x * blockDim.x + threadIdx.x;   // 16384 threads
    {
        int lane = idx & 31;
        int ntg  = (idx >> 5) & 15;
        int ks   = (idx >> 9) & 3;
        int c    = idx >> 11;
        if (c < NCHUNK) {
            int g = lane >> 2, t = lane & 3;
            int n = c * CPC + ntg * 8 + g;
            const float* e = emb + (size_t)n * DDIM + ks * 16;
            g_bfrag[c][ks][ntg][lane] =
                make_uint2(packh(e[2 * t], e[2 * t + 1]),
                           packh(e[2 * t + 8], e[2 * t + 9]));
        }
    }
    if (idx < KCODES) {
        const float4* e = (const float4*)(emb + (size_t)idx * DDIM);
        float s = 0.f;
#pragma unroll
        for (int i = 0; i < 16; i++) {
            float4 v = e[i];
            s += v.x * v.x + v.y * v.y + v.z * v.z + v.w * v.w;
        }
        g_esq[idx] = s;
    }
}

// ---------------- main kernel: 16 rows/warp, 1-pass fp16, keyed top-3, 4 CTAs/SM ----------------
__global__ __launch_bounds__(BLOCK, 4) void vq_main(
    const float* __restrict__ x, const float* __restrict__ emb,
    float* __restrict__ out, int N)
{
    __shared__ uint2 s_bfrag[2][4][16][32];   // 2 x 16 KB double buffer
    __shared__ float s_esq[KCODES];           // 4 KB
    __shared__ float s_red[BLOCK / 32];
    const uint32_t sb_frag = smem_u32(&s_bfrag[0][0][0][0]);

    const int tid = threadIdx.x, wid = tid >> 5, lane = tid & 31;
    const int g = lane >> 2, t = lane & 3;
    const int base = blockIdx.x * 128 + wid * 16;   // 16 rows per warp

    // ---- A fragments: plain fp16 (rescore machinery absorbs the error) ----
    uint32_t Ah[4][4];
    {
        const float* r0 = x + (size_t)(base + g) * DDIM;
        const float* r8 = r0 + 8 * DDIM;
#pragma unroll
        for (int ks = 0; ks < 4; ks++) {
            const float2* p0 = (const float2*)(r0 + ks * 16);
            const float2* p8 = (const float2*)(r8 + ks * 16);
            float2 v0a = p0[t], v0b = p0[t + 4];
            float2 v8a = p8[t], v8b = p8[t + 4];
            Ah[ks][0] = packh(v0a.x, v0a.y);
            Ah[ks][1] = packh(v8a.x, v8a.y);
            Ah[ks][2] = packh(v0b.x, v0b.y);
            Ah[ks][3] = packh(v8b.x, v8b.y);
        }
    }

    // ---- esq into smem + prefetch chunk 0 (16 KB) ----
    {
        const char* src = (const char*)&g_bfrag[0][0][0][0];
#pragma unroll
        for (int i = 0; i < 4; i++)
            CP_ASYNC16(sb_frag + tid * 16 + i * 4096, src + tid * 16 + i * 4096);
        CP_COMMIT();
        for (int i = tid; i < KCODES; i += BLOCK) s_esq[i] = g_esq[i];
    }
    CP_WAIT0();
    __syncthreads();

    // keyed top-3 per row (j=0: row g, j=1: row g+8), 10-bit global code key
    float fc1[2] = {3.4e38f, 3.4e38f};
    float fc2[2] = {3.4e38f, 3.4e38f};
    float fc3[2] = {3.4e38f, 3.4e38f};

#define TOP3_INS(j, dist, code) do {                                \
        float _f = keyed(dist, code);                               \
        float _t0 = fmaxf(fc1[j], _f); fc1[j] = fminf(fc1[j], _f);  \
        float _t1 = fmaxf(fc2[j], _t0); fc2[j] = fminf(fc2[j], _t0);\
        fc3[j] = fminf(fc3[j], _t1);                                \
    } while (0)

    for (int c = 0; c < NCHUNK; c++) {
        const int cur = c & 1;
        if (c < NCHUNK - 1) {   // prefetch next chunk into other buffer
            const char* src = (const char*)&g_bfrag[c + 1][0][0][0];
            const uint32_t dst = sb_frag + (cur ^ 1) * 16384;
#pragma unroll
            for (int i = 0; i < 4; i++)
                CP_ASYNC16(dst + tid * 16 + i * 4096, src + tid * 16 + i * 4096);
            CP_COMMIT();
        }
        const uint2* bf = &s_bfrag[cur][0][0][0];

        for (int sub = 0; sub < NSUB; sub++) {
            float acc[4][4];
#pragma unroll
            for (int nt = 0; nt < 4; nt++)
#pragma unroll
                for (int q = 0; q < 4; q++) acc[nt][q] = 0.f;

            // single fp16 pass: dot = fl16(x) . fl16(e), fp32 accumulate
#pragma unroll
            for (int ks = 0; ks < 4; ks++) {
                uint2 b[4];
#pragma unroll
                for (int nt = 0; nt < 4; nt++)
                    b[nt] = bf[(ks * 16 + sub * 4 + nt) * 32 + lane];
#pragma unroll
                for (int nt = 0; nt < 4; nt++)
                    MMA16816(acc[nt], Ah[ks], b[nt].x, b[nt].y);
            }

            // epilogue: dist = esq - 2*dot, keyed top-3 (R12 streaming form)
#pragma unroll
            for (int nt = 0; nt < 4; nt++) {
                const int ntg = sub * 4 + nt;
                float2 es = *(const float2*)&s_esq[c * CPC + ntg * 8 + 2 * t];
                const uint32_t k0 = (uint32_t)(c * CPC + ntg * 8 + 2 * t);
                TOP3_INS(0, fmaf(-2.f, acc[nt][0], es.x), k0);
                TOP3_INS(0, fmaf(-2.f, acc[nt][1], es.y), k0 + 1);
                TOP3_INS(1, fmaf(-2.f, acc[nt][2], es.x), k0);
                TOP3_INS(1, fmaf(-2.f, acc[nt][3], es.y), k0 + 1);
            }
        }

        if (c < NCHUNK - 1) CP_WAIT0();
        __syncthreads();
    }

    // ---- merge sorted top-3 across the 4-lane t-group (keyed values are distinct) ----
#pragma unroll
    for (int off = 1; off <= 2; off <<= 1) {
#pragma unroll
        for (int j = 0; j < 2; j++) {
            float o1 = __shfl_xor_sync(0xffffffffu, fc1[j], off);
            float o2 = __shfl_xor_sync(0xffffffffu, fc2[j], off);
            float o3 = __shfl_xor_sync(0xffffffffu, fc3[j], off);
            float hi1 = fmaxf(fc1[j], o1), c1 = fminf(fc1[j], o1);
            float lo2 = fminf(fc2[j], o2), hi2 = fmaxf(fc2[j], o2);
            float lo3 = fminf(fc3[j], o3);
            float c2 = fminf(hi1, lo2);
            float c3 = fminf(fmaxf(hi1, lo2), fminf(hi2, lo3));
            fc1[j] = c1; fc2[j] = c2; fc3[j] = c3;
        }
    }

    // ---- decode + near-tie rescore with the REFERENCE's coarse fp32 arithmetic ----
    int gi[2];
#pragma unroll
    for (int j = 0; j < 2; j++) {
        uint32_t b1 = __float_as_uint(fc1[j]);
        uint32_t b2 = __float_as_uint(fc2[j]);
        uint32_t b3 = __float_as_uint(fc3[j]);
        int   i1 = (int)(b1 & 1023u), i2 = (int)(b2 & 1023u), i3 = (int)(b3 & 1023u);
        float f1 = __uint_as_float(b1 & 0xFFFFFC00u);
        float f2 = __uint_as_float(b2 & 0xFFFFFC00u);
        float f3 = __uint_as_float(b3 & 0xFFFFFC00u);
        gi[j] = i1;
        if (f2 - f1 < RESCORE_TAU) {
            const int row = base + j * 8 + g;
            const float* xr = x + (size_t)row * DDIM;
            float xsq = 0.f;
            for (int k = 0; k < DDIM; k++)
                xsq = __fadd_rn(xsq, __fmul_rn(xr[k], xr[k]));
            const bool use3 = (f3 - f1 < RESCORE_TAU);
            const float* e1 = emb + (size_t)i1 * DDIM;
            const float* e2 = emb + (size_t)i2 * DDIM;
            const float* e3 = emb + (size_t)i3 * DDIM;
            double d1 = 0.0, d2 = 0.0, d3 = 0.0;
            for (int k = 0; k < DDIM; k++) {
                double xv = (double)xr[k];
                d1 = fma(xv, (double)e1[k], d1);
                d2 = fma(xv, (double)e2[k], d2);
                if (use3) d3 = fma(xv, (double)e3[k], d3);
            }
            float c1d = coarse_dist(xsq, g_esq[i1], (float)d1);
            float c2d = coarse_dist(xsq, g_esq[i2], (float)d2);
            int   bi = i1; float bd = c1d;
            if (c2d < bd || (c2d == bd && i2 < bi)) { bd = c2d; bi = i2; }
            if (use3) {
                float c3d = coarse_dist(xsq, g_esq[i3], (float)d3);
                if (c3d < bd || (c3d == bd && i3 < bi)) { bd = c3d; bi = i3; }
            }
            gi[j] = bi;
        }
    }

    // ---- outputs: quant gather (exact fp32), indices, exact loss partial ----
    float errsum = 0.f;
#pragma unroll
    for (int j = 0; j < 2; j++) {
        const int row = base + j * 8 + g;
        const int idx = gi[j];
        if (t == 0) out[(size_t)N * DDIM + 1 + row] = (float)idx;
        const float4* ep = (const float4*)(emb + (size_t)idx * DDIM + t * 16);
        const float4* xp = (const float4*)(x + (size_t)row * DDIM + t * 16);
        float4* op = (float4*)(out + (size_t)row * DDIM + t * 16);
#pragma unroll
        for (int q = 0; q < 4; q++) {
            float4 e = ep[q], v = xp[q];
            op[q] = e;
            float d0 = e.x - v.x, d1 = e.y - v.y, d2 = e.z - v.z, d3 = e.w - v.w;
            errsum += d0 * d0 + d1 * d1 + d2 * d2 + d3 * d3;
        }
    }
#pragma unroll
    for (int o = 16; o; o >>= 1) errsum += __shfl_down_sync(0xffffffffu, errsum, o);
    if (lane == 0) s_red[wid] = errsum;
    __syncthreads();
    if (tid == 0) {
        float s = 0.f;
#pragma unroll
        for (int w = 0; w < BLOCK / 32; w++) s += s_red[w];
        g_partials[blockIdx.x] = s;
    }
}

// ---------------- final loss reduction (1024 threads = 32 warps) ----------------
__global__ void loss_kernel(float* __restrict__ out, int nblocks, int N) {
    __shared__ float s_red[32];
    float v = 0.f;
    for (int i = threadIdx.x; i < nblocks; i += blockDim.x) v += g_partials[i];
#pragma unroll
    for (int o = 16; o; o >>= 1) v += __shfl_down_sync(0xffffffffu, v, o);
    if ((threadIdx.x & 31) == 0) s_red[threadIdx.x >> 5] = v;
    __syncthreads();
    if (threadIdx.x < 32) {
        float tt = (threadIdx.x < (int)(blockDim.x >> 5)) ? s_red[threadIdx.x] : 0.f;
#pragma unroll
        for (int o = 16; o; o >>= 1) tt += __shfl_down_sync(0xffffffffu, tt, o);
        if (threadIdx.x == 0)
            out[(size_t)N * DDIM] = 1.25f * tt / ((float)N * (float)DDIM);
    }
}

// ---------------------------------------------------------------------------
extern "C" void kernel_launch(void* const* d_in, const int* in_sizes, int n_in,
                              void* d_out, int out_size) {
    const float* x   = (const float*)d_in[0];   // [B,T,D] fp32
    const float* emb = (const float*)d_in[1];   // [K,D]  fp32
    float* out = (float*)d_out;                 // [N*D quant | 1 loss | N idx]
    const int N  = in_sizes[0] / DDIM;          // 131072
    const int nb = N / 128;                     // 1024

    prep<<<64, 256>>>(emb);
    vq_main<<<nb, BLOCK>>>(x, emb, out, N);
    loss_kernel<<<1, 1024>>>(out, nb, N);
}

// round 15
// speedup vs baseline: 1.0710x; 1.0039x over previous
#include <cuda_runtime.h>
#include <cuda_fp16.h>
#include <cstdint>

#define DDIM    64
#define KCODES  1024
#define NCHUNK  8
#define CPC     128          // codes per chunk
#define NSUB    4            // n32 subtiles per chunk
#define BLOCK   128          // 4 warps, 32 rows/warp -> 128 rows per block
#define RESCORE_TAU 2e-3f

// ---------------- device scratch (allocation-free rule) ----------------
__device__ float g_esq[KCODES];
// fp16 codebook fragments: [chunk][ks(4)][ntile(16)][lane(32)] -> {b0,b1}  (128 KB)
__device__ uint2 g_bfrag[NCHUNK][4][16][32];
__device__ float g_partials[1024];

// ---------------- helpers ----------------
__device__ __forceinline__ uint32_t packh(float lo, float hi) {
    __half2 h = __floats2half2_rn(lo, hi);
    return *reinterpret_cast<uint32_t*>(&h);
}
#define MMA16816(D, A, b0v, b1v)                                             \
    asm volatile("mma.sync.aligned.m16n8k16.row.col.f32.f16.f16.f32 "        \
                 "{%0,%1,%2,%3}, {%4,%5,%6,%7}, {%8,%9}, {%0,%1,%2,%3};"     \
                 : "+f"((D)[0]), "+f"((D)[1]), "+f"((D)[2]), "+f"((D)[3])    \
                 : "r"((A)[0]), "r"((A)[1]), "r"((A)[2]), "r"((A)[3]),       \
                   "r"(b0v), "r"(b1v))

#define CP_ASYNC16(saddr, gptr) \
    asm volatile("cp.async.cg.shared.global [%0], [%1], 16;" :: "r"(saddr), "l"(gptr) : "memory")
#define CP_COMMIT() asm volatile("cp.async.commit_group;" ::: "memory")
#define CP_WAIT0()  asm volatile("cp.async.wait_group 0;" ::: "memory")

__device__ __forceinline__ uint32_t smem_u32(const void* p) {
    uint32_t a;
    asm("{ .reg .u64 t; cvta.to.shared.u64 t, %1; cvt.u32.u64 %0, t; }" : "=r"(a) : "l"(p));
    return a;
}
// reference-coarse distance: fl32(fl32(xsq+esq) - fl32(2*dot))
__device__ __forceinline__ float coarse_dist(float xsq, float esq, float dotf) {
    float t = __fadd_rn(xsq, esq);
    return __fadd_rn(t, -__fmul_rn(2.0f, dotf));
}
// embed 10-bit GLOBAL code into low mantissa bits
__device__ __forceinline__ float keyed(float d, uint32_t code) {
    return __uint_as_float((__float_as_uint(d) & 0xFFFFFC00u) | code);
}

// ---------------- prep (merged): |e|^2 + fp16 B fragments ----------------
// NEEDS >= 16384 threads: one thread per g_bfrag entry.
__global__ void prep(const float* __restrict__ emb) {
    int idx = blockIdx.x * blockDim.x + threadIdx.x;   // 16384 threads
    {
        int lane = idx & 31;
        int ntg  = (idx >> 5) & 15;
        int ks   = (idx >> 9) & 3;
        int c    = idx >> 11;
        if (c < NCHUNK) {
            int g = lane >> 2, t = lane & 3;
            int n = c * CPC + ntg * 8 + g;
            const float* e = emb + (size_t)n * DDIM + ks * 16;
            g_bfrag[c][ks][ntg][lane] =
                make_uint2(packh(e[2 * t], e[2 * t + 1]),
                           packh(e[2 * t + 8], e[2 * t + 9]));
        }
    }
    if (idx < KCODES) {
        const float4* e = (const float4*)(emb + (size_t)idx * DDIM);
        float s = 0.f;
#pragma unroll
        for (int i = 0; i < 16; i++) {
            float4 v = e[i];
            s += v.x * v.x + v.y * v.y + v.z * v.z + v.w * v.w;
        }
        g_esq[idx] = s;
    }
}

// ---------------- main: 32 rows/warp (B reused x2), 1-pass fp16, keyed top-3 ----------------
__global__ __launch_bounds__(BLOCK, 4) void vq_main(
    const float* __restrict__ x, const float* __restrict__ emb,
    float* __restrict__ out, int N)
{
    __shared__ uint2 s_bfrag[2][4][16][32];   // 2 x 16 KB double buffer
    __shared__ float s_esq[KCODES];           // 4 KB
    __shared__ float s_red[BLOCK / 32];
    const uint32_t sb_frag = smem_u32(&s_bfrag[0][0][0][0]);

    const int tid = threadIdx.x, wid = tid >> 5, lane = tid & 31;
    const int g = lane >> 2, t = lane & 3;
    const int base = blockIdx.x * 128 + wid * 32;   // 32 rows per warp

    // ---- A fragments: plain fp16, two m16 tiles (mt=0,1) ----
    uint32_t Ah[2][4][4];
#pragma unroll
    for (int mt = 0; mt < 2; mt++) {
        const float* r0 = x + (size_t)(base + mt * 16 + g) * DDIM;
        const float* r8 = r0 + 8 * DDIM;
#pragma unroll
        for (int ks = 0; ks < 4; ks++) {
            const float2* p0 = (const float2*)(r0 + ks * 16);
            const float2* p8 = (const float2*)(r8 + ks * 16);
            float2 v0a = p0[t], v0b = p0[t + 4];
            float2 v8a = p8[t], v8b = p8[t + 4];
            Ah[mt][ks][0] = packh(v0a.x, v0a.y);
            Ah[mt][ks][1] = packh(v8a.x, v8a.y);
            Ah[mt][ks][2] = packh(v0b.x, v0b.y);
            Ah[mt][ks][3] = packh(v8b.x, v8b.y);
        }
    }

    // ---- esq into smem + prefetch chunk 0 (16 KB, 128 threads -> 8 iters) ----
    {
        const char* src = (const char*)&g_bfrag[0][0][0][0];
#pragma unroll
        for (int i = 0; i < 8; i++)
            CP_ASYNC16(sb_frag + tid * 16 + i * 2048, src + tid * 16 + i * 2048);
        CP_COMMIT();
        for (int i = tid; i < KCODES; i += BLOCK) s_esq[i] = g_esq[i];
    }
    CP_WAIT0();
    __syncthreads();

    // keyed top-3 per row slot j = mt*2 + h (rows: base + mt*16 + h*8 + g)
    float fc1[4] = {3.4e38f, 3.4e38f, 3.4e38f, 3.4e38f};
    float fc2[4] = {3.4e38f, 3.4e38f, 3.4e38f, 3.4e38f};
    float fc3[4] = {3.4e38f, 3.4e38f, 3.4e38f, 3.4e38f};

#define TOP3_INS(j, dist, code) do {                                \
        float _f = keyed(dist, code);                               \
        float _t0 = fmaxf(fc1[j], _f); fc1[j] = fminf(fc1[j], _f);  \
        float _t1 = fmaxf(fc2[j], _t0); fc2[j] = fminf(fc2[j], _t0);\
        fc3[j] = fminf(fc3[j], _t1);                                \
    } while (0)

    for (int c = 0; c < NCHUNK; c++) {
        const int cur = c & 1;
        if (c < NCHUNK - 1) {   // prefetch next chunk into other buffer
            const char* src = (const char*)&g_bfrag[c + 1][0][0][0];
            const uint32_t dst = sb_frag + (cur ^ 1) * 16384;
#pragma unroll
            for (int i = 0; i < 8; i++)
                CP_ASYNC16(dst + tid * 16 + i * 2048, src + tid * 16 + i * 2048);
            CP_COMMIT();
        }
        const uint2* bf = &s_bfrag[cur][0][0][0];

        for (int sub = 0; sub < NSUB; sub++) {
            float acc[2][4][4];
#pragma unroll
            for (int mt = 0; mt < 2; mt++)
#pragma unroll
                for (int nt = 0; nt < 4; nt++)
#pragma unroll
                    for (int q = 0; q < 4; q++) acc[mt][nt][q] = 0.f;

            // 1-pass fp16: each b fragment feeds BOTH m16 tiles
#pragma unroll
            for (int ks = 0; ks < 4; ks++) {
                uint2 b[4];
#pragma unroll
                for (int nt = 0; nt < 4; nt++)
                    b[nt] = bf[(ks * 16 + sub * 4 + nt) * 32 + lane];
#pragma unroll
                for (int nt = 0; nt < 4; nt++) {
                    MMA16816(acc[0][nt], Ah[0][ks], b[nt].x, b[nt].y);
                    MMA16816(acc[1][nt], Ah[1][ks], b[nt].x, b[nt].y);
                }
            }

            // epilogue: dist = esq - 2*dot, keyed top-3 (es shared across mt)
#pragma unroll
            for (int nt = 0; nt < 4; nt++) {
                const int ntg = sub * 4 + nt;
                float2 es = *(const float2*)&s_esq[c * CPC + ntg * 8 + 2 * t];
                const uint32_t k0 = (uint32_t)(c * CPC + ntg * 8 + 2 * t);
#pragma unroll
                for (int mt = 0; mt < 2; mt++) {
                    TOP3_INS(mt * 2 + 0, fmaf(-2.f, acc[mt][nt][0], es.x), k0);
                    TOP3_INS(mt * 2 + 0, fmaf(-2.f, acc[mt][nt][1], es.y), k0 + 1);
                    TOP3_INS(mt * 2 + 1, fmaf(-2.f, acc[mt][nt][2], es.x), k0);
                    TOP3_INS(mt * 2 + 1, fmaf(-2.f, acc[mt][nt][3], es.y), k0 + 1);
                }
            }
        }

        if (c < NCHUNK - 1) CP_WAIT0();
        __syncthreads();
    }

    // ---- merge sorted top-3 across the 4-lane t-group (keyed values are distinct) ----
#pragma unroll
    for (int off = 1; off <= 2; off <<= 1) {
#pragma unroll
        for (int j = 0; j < 4; j++) {
            float o1 = __shfl_xor_sync(0xffffffffu, fc1[j], off);
            float o2 = __shfl_xor_sync(0xffffffffu, fc2[j], off);
            float o3 = __shfl_xor_sync(0xffffffffu, fc3[j], off);
            float hi1 = fmaxf(fc1[j], o1), c1 = fminf(fc1[j], o1);
            float lo2 = fminf(fc2[j], o2), hi2 = fmaxf(fc2[j], o2);
            float lo3 = fminf(fc3[j], o3);
            float c2 = fminf(hi1, lo2);
            float c3 = fminf(fmaxf(hi1, lo2), fminf(hi2, lo3));
            fc1[j] = c1; fc2[j] = c2; fc3[j] = c3;
        }
    }

    // ---- decode + near-tie rescore with the REFERENCE's coarse fp32 arithmetic ----
    int gi[4];
#pragma unroll
    for (int j = 0; j < 4; j++) {
        uint32_t b1 = __float_as_uint(fc1[j]);
        uint32_t b2 = __float_as_uint(fc2[j]);
        uint32_t b3 = __float_as_uint(fc3[j]);
        int   i1 = (int)(b1 & 1023u), i2 = (int)(b2 & 1023u), i3 = (int)(b3 & 1023u);
        float f1 = __uint_as_float(b1 & 0xFFFFFC00u);
        float f2 = __uint_as_float(b2 & 0xFFFFFC00u);
        float f3 = __uint_as_float(b3 & 0xFFFFFC00u);
        gi[j] = i1;
        if (f2 - f1 < RESCORE_TAU) {
            const int row = base + (j >> 1) * 16 + (j & 1) * 8 + g;
            const float* xr = x + (size_t)row * DDIM;
            float xsq = 0.f;
            for (int k = 0; k < DDIM; k++)
                xsq = __fadd_rn(xsq, __fmul_rn(xr[k], xr[k]));
            const bool use3 = (f3 - f1 < RESCORE_TAU);
            const float* e1 = emb + (size_t)i1 * DDIM;
            const float* e2 = emb + (size_t)i2 * DDIM;
            const float* e3 = emb + (size_t)i3 * DDIM;
            double d1 = 0.0, d2 = 0.0, d3 = 0.0;
            for (int k = 0; k < DDIM; k++) {
                double xv = (double)xr[k];
                d1 = fma(xv, (double)e1[k], d1);
                d2 = fma(xv, (double)e2[k], d2);
                if (use3) d3 = fma(xv, (double)e3[k], d3);
            }
            float c1d = coarse_dist(xsq, g_esq[i1], (float)d1);
            float c2d = coarse_dist(xsq, g_esq[i2], (float)d2);
            int   bi = i1; float bd = c1d;
            if (c2d < bd || (c2d == bd && i2 < bi)) { bd = c2d; bi = i2; }
            if (use3) {
                float c3d = coarse_dist(xsq, g_esq[i3], (float)d3);
                if (c3d < bd || (c3d == bd && i3 < bi)) { bd = c3d; bi = i3; }
            }
            gi[j] = bi;
        }
    }

    // ---- outputs: quant gather (exact fp32), indices, exact loss partial ----
    float errsum = 0.f;
#pragma unroll
    for (int j = 0; j < 4; j++) {
        const int row = base + (j >> 1) * 16 + (j & 1) * 8 + g;
        const int idx = gi[j];
        if (t == 0) out[(size_t)N * DDIM + 1 + row] = (float)idx;
        const float4* ep = (const float4*)(emb + (size_t)idx * DDIM + t * 16);
        const float4* xp = (const float4*)(x + (size_t)row * DDIM + t * 16);
        float4* op = (float4*)(out + (size_t)row * DDIM + t * 16);
#pragma unroll
        for (int q = 0; q < 4; q++) {
            float4 e = ep[q], v = xp[q];
            op[q] = e;
            float d0 = e.x - v.x, d1 = e.y - v.y, d2 = e.z - v.z, d3 = e.w - v.w;
            errsum += d0 * d0 + d1 * d1 + d2 * d2 + d3 * d3;
        }
    }
#pragma unroll
    for (int o = 16; o; o >>= 1) errsum += __shfl_down_sync(0xffffffffu, errsum, o);
    if (lane == 0) s_red[wid] = errsum;
    __syncthreads();
    if (tid == 0) {
        float s = 0.f;
#pragma unroll
        for (int w = 0; w < BLOCK / 32; w++) s += s_red[w];
        g_partials[blockIdx.x] = s;
    }
}

// ---------------- final loss reduction (1024 threads = 32 warps) ----------------
__global__ void loss_kernel(float* __restrict__ out, int nblocks, int N) {
    __shared__ float s_red[32];
    float v = 0.f;
    for (int i = threadIdx.x; i < nblocks; i += blockDim.x) v += g_partials[i];
#pragma unroll
    for (int o = 16; o; o >>= 1) v += __shfl_down_sync(0xffffffffu, v, o);
    if ((threadIdx.x & 31) == 0) s_red[threadIdx.x >> 5] = v;
    __syncthreads();
    if (threadIdx.x < 32) {
        float tt = (threadIdx.x < (int)(blockDim.x >> 5)) ? s_red[threadIdx.x] : 0.f;
#pragma unroll
        for (int o = 16; o; o >>= 1) tt += __shfl_down_sync(0xffffffffu, tt, o);
        if (threadIdx.x == 0)
            out[(size_t)N * DDIM] = 1.25f * tt / ((float)N * (float)DDIM);
    }
}

// ---------------------------------------------------------------------------
extern "C" void kernel_launch(void* const* d_in, const int* in_sizes, int n_in,
                              void* d_out, int out_size) {
    const float* x   = (const float*)d_in[0];   // [B,T,D] fp32
    const float* emb = (const float*)d_in[1];   // [K,D]  fp32
    float* out = (float*)d_out;                 // [N*D quant | 1 loss | N idx]
    const int N  = in_sizes[0] / DDIM;          // 131072
    const int nb = N / 128;                     // 1024

    prep<<<64, 256>>>(emb);
    vq_main<<<nb, BLOCK>>>(x, emb, out, N);
    loss_kernel<<<1, 1024>>>(out, nb, N);
}